// round 1
// baseline (speedup 1.0000x reference)
#include <cuda_runtime.h>
#include <math.h>

#define BB 2
#define SEQ 2048
#define DMODEL 1024
#define NH 16
#define HD 64
#define QKV_ELEMS (BB * SEQ * DMODEL)

// Scratch (no allocations allowed) — 4 x 16 MB
__device__ float g_q[QKV_ELEMS];
__device__ float g_k[QKV_ELEMS];
__device__ float g_v[QKV_ELEMS];
__device__ float g_ctx[QKV_ELEMS];

// ---------------------------------------------------------------------------
// Generic 128x128x8 SGEMM (NN) with bias: C[M,N] = A[M,K] @ B[K,N] + bias[N]
// Strides: lda=K, ldb=N, ldc=N. M,N multiples of 128, K multiple of 8.
// 256 threads, 8x8 accumulators per thread (split 4+4 to keep smem loads wide).
// ---------------------------------------------------------------------------
__global__ __launch_bounds__(256) void sgemm_nn_bias(
    const float* __restrict__ A, const float* __restrict__ B,
    const float* __restrict__ bias, float* __restrict__ C,
    int M, int N, int K)
{
    __shared__ float As[8][128];
    __shared__ float Bs[8][128];
    const int tid = threadIdx.x;
    const int tx = tid & 15, ty = tid >> 4;
    const int rowBase = blockIdx.y * 128, colBase = blockIdx.x * 128;
    const int ar = tid >> 1, ac = (tid & 1) * 4;
    const int br = tid >> 5, bc = (tid & 31) * 4;
    const float* Aptr = A + (size_t)(rowBase + ar) * K + ac;
    const float* Bptr = B + (size_t)br * N + colBase + bc;

    float acc[8][8];
#pragma unroll
    for (int i = 0; i < 8; i++)
#pragma unroll
        for (int j = 0; j < 8; j++) acc[i][j] = 0.0f;

    for (int k0 = 0; k0 < K; k0 += 8) {
        float4 av = *(const float4*)(Aptr + k0);
        float4 bv = *(const float4*)(Bptr + (size_t)k0 * N);
        As[ac + 0][ar] = av.x; As[ac + 1][ar] = av.y;
        As[ac + 2][ar] = av.z; As[ac + 3][ar] = av.w;
        *(float4*)&Bs[br][bc] = bv;
        __syncthreads();
#pragma unroll
        for (int k = 0; k < 8; k++) {
            float a[8], b[8];
            *(float4*)(a)     = *(const float4*)&As[k][ty * 4];
            *(float4*)(a + 4) = *(const float4*)&As[k][64 + ty * 4];
            *(float4*)(b)     = *(const float4*)&Bs[k][tx * 4];
            *(float4*)(b + 4) = *(const float4*)&Bs[k][64 + tx * 4];
#pragma unroll
            for (int i = 0; i < 8; i++)
#pragma unroll
                for (int j = 0; j < 8; j++)
                    acc[i][j] += a[i] * b[j];
        }
        __syncthreads();
    }

#pragma unroll
    for (int i = 0; i < 8; i++) {
        int row = rowBase + ((i < 4) ? (ty * 4 + i) : (64 + ty * 4 + (i - 4)));
#pragma unroll
        for (int jh = 0; jh < 2; jh++) {
            int col = colBase + jh * 64 + tx * 4;
            float4 bb = *(const float4*)&bias[col];
            float4 r;
            r.x = acc[i][jh * 4 + 0] + bb.x;
            r.y = acc[i][jh * 4 + 1] + bb.y;
            r.z = acc[i][jh * 4 + 2] + bb.z;
            r.w = acc[i][jh * 4 + 3] + bb.w;
            *(float4*)&C[(size_t)row * N + col] = r;
        }
    }
}

// ---------------------------------------------------------------------------
// Scores: for each (b,h): S = 0.125 * Qbh[2048,64] @ Kbh[2048,64]^T
// Q/K layout [B,S,H,HD] -> row stride DMODEL, base offset b*SEQ*DMODEL + h*HD.
// Writes raw (pre-softmax) scores into the attn output region.
// ---------------------------------------------------------------------------
__global__ __launch_bounds__(256) void scores_kernel(float* __restrict__ attn)
{
    __shared__ float As[8][128];
    __shared__ float Bs[8][128];
    const int tid = threadIdx.x;
    const int tx = tid & 15, ty = tid >> 4;
    const int z = blockIdx.z;            // b*NH + h
    const int b = z >> 4, h = z & 15;
    const int rowBase = blockIdx.y * 128, colBase = blockIdx.x * 128;
    const float* Qb = g_q + (size_t)b * SEQ * DMODEL + h * HD;
    const float* Kb = g_k + (size_t)b * SEQ * DMODEL + h * HD;
    const int ar = tid >> 1, ac = (tid & 1) * 4;
    const float* Aptr = Qb + (size_t)(rowBase + ar) * DMODEL + ac;
    const float* Bptr = Kb + (size_t)(colBase + ar) * DMODEL + ac;

    float acc[8][8];
#pragma unroll
    for (int i = 0; i < 8; i++)
#pragma unroll
        for (int j = 0; j < 8; j++) acc[i][j] = 0.0f;

#pragma unroll
    for (int k0 = 0; k0 < HD; k0 += 8) {
        float4 av = *(const float4*)(Aptr + k0);
        float4 bv = *(const float4*)(Bptr + k0);
        As[ac + 0][ar] = av.x; As[ac + 1][ar] = av.y;
        As[ac + 2][ar] = av.z; As[ac + 3][ar] = av.w;
        Bs[ac + 0][ar] = bv.x; Bs[ac + 1][ar] = bv.y;
        Bs[ac + 2][ar] = bv.z; Bs[ac + 3][ar] = bv.w;
        __syncthreads();
#pragma unroll
        for (int k = 0; k < 8; k++) {
            float a[8], bfr[8];
            *(float4*)(a)       = *(const float4*)&As[k][ty * 4];
            *(float4*)(a + 4)   = *(const float4*)&As[k][64 + ty * 4];
            *(float4*)(bfr)     = *(const float4*)&Bs[k][tx * 4];
            *(float4*)(bfr + 4) = *(const float4*)&Bs[k][64 + tx * 4];
#pragma unroll
            for (int i = 0; i < 8; i++)
#pragma unroll
                for (int j = 0; j < 8; j++)
                    acc[i][j] += a[i] * bfr[j];
        }
        __syncthreads();
    }

    float* Cb = attn + (size_t)z * SEQ * SEQ;
#pragma unroll
    for (int i = 0; i < 8; i++) {
        int row = rowBase + ((i < 4) ? (ty * 4 + i) : (64 + ty * 4 + (i - 4)));
#pragma unroll
        for (int jh = 0; jh < 2; jh++) {
            int col = colBase + jh * 64 + tx * 4;
            float4 r;
            r.x = acc[i][jh * 4 + 0] * 0.125f;
            r.y = acc[i][jh * 4 + 1] * 0.125f;
            r.z = acc[i][jh * 4 + 2] * 0.125f;
            r.w = acc[i][jh * 4 + 3] * 0.125f;
            *(float4*)&Cb[(size_t)row * SEQ + col] = r;
        }
    }
}

// ---------------------------------------------------------------------------
// Softmax over one 2048-wide row per block, in-place.
// ---------------------------------------------------------------------------
__global__ __launch_bounds__(256) void softmax_kernel(float* __restrict__ attn)
{
    const int tid = threadIdx.x;
    float* p = attn + (size_t)blockIdx.x * SEQ;
    float4 v0 = ((const float4*)p)[tid];
    float4 v1 = ((const float4*)p)[tid + 256];

    float m = fmaxf(fmaxf(fmaxf(v0.x, v0.y), fmaxf(v0.z, v0.w)),
                    fmaxf(fmaxf(v1.x, v1.y), fmaxf(v1.z, v1.w)));
    __shared__ float red[8];
#pragma unroll
    for (int o = 16; o > 0; o >>= 1) m = fmaxf(m, __shfl_xor_sync(0xffffffffu, m, o));
    if ((tid & 31) == 0) red[tid >> 5] = m;
    __syncthreads();
    m = fmaxf(fmaxf(fmaxf(red[0], red[1]), fmaxf(red[2], red[3])),
              fmaxf(fmaxf(red[4], red[5]), fmaxf(red[6], red[7])));
    __syncthreads();

    float e[8];
    e[0] = expf(v0.x - m); e[1] = expf(v0.y - m);
    e[2] = expf(v0.z - m); e[3] = expf(v0.w - m);
    e[4] = expf(v1.x - m); e[5] = expf(v1.y - m);
    e[6] = expf(v1.z - m); e[7] = expf(v1.w - m);
    float s = ((e[0] + e[1]) + (e[2] + e[3])) + ((e[4] + e[5]) + (e[6] + e[7]));
#pragma unroll
    for (int o = 16; o > 0; o >>= 1) s += __shfl_xor_sync(0xffffffffu, s, o);
    if ((tid & 31) == 0) red[tid >> 5] = s;
    __syncthreads();
    s = ((red[0] + red[1]) + (red[2] + red[3])) + ((red[4] + red[5]) + (red[6] + red[7]));
    float inv = 1.0f / s;

    float4 w0, w1;
    w0.x = e[0] * inv; w0.y = e[1] * inv; w0.z = e[2] * inv; w0.w = e[3] * inv;
    w1.x = e[4] * inv; w1.y = e[5] * inv; w1.z = e[6] * inv; w1.w = e[7] * inv;
    ((float4*)p)[tid] = w0;
    ((float4*)p)[tid + 256] = w1;
}

// ---------------------------------------------------------------------------
// ctx = attn @ V per (b,h): [2048,2048] @ [2048,64] -> g_ctx in [B,S,H,HD].
// Tile: BM=128, BN=64 (full HD), BK=16, 256 threads, 4x8 accum per thread.
// ---------------------------------------------------------------------------
__global__ __launch_bounds__(256) void ctx_kernel(const float* __restrict__ attn)
{
    __shared__ float Ps[16][128];
    __shared__ float Vs[16][64];
    const int tid = threadIdx.x;
    const int z = blockIdx.z;
    const int b = z >> 4, h = z & 15;
    const int rowBase = blockIdx.y * 128;
    const float* P = attn + (size_t)z * SEQ * SEQ;
    const float* V = g_v + (size_t)b * SEQ * DMODEL + h * HD;
    const int pr = tid >> 1, pc = (tid & 1) * 8;
    const int vr = tid >> 4, vc = (tid & 15) * 4;
    const int tx = tid & 7, ty = tid >> 3;

    float acc[4][8];
#pragma unroll
    for (int i = 0; i < 4; i++)
#pragma unroll
        for (int j = 0; j < 8; j++) acc[i][j] = 0.0f;

    const float* Prow = P + (size_t)(rowBase + pr) * SEQ;
    for (int k0 = 0; k0 < SEQ; k0 += 16) {
        float4 p0 = *(const float4*)(Prow + k0 + pc);
        float4 p1 = *(const float4*)(Prow + k0 + pc + 4);
        float4 vv = *(const float4*)(V + (size_t)(k0 + vr) * DMODEL + vc);
        Ps[pc + 0][pr] = p0.x; Ps[pc + 1][pr] = p0.y;
        Ps[pc + 2][pr] = p0.z; Ps[pc + 3][pr] = p0.w;
        Ps[pc + 4][pr] = p1.x; Ps[pc + 5][pr] = p1.y;
        Ps[pc + 6][pr] = p1.z; Ps[pc + 7][pr] = p1.w;
        *(float4*)&Vs[vr][vc] = vv;
        __syncthreads();
#pragma unroll
        for (int k = 0; k < 16; k++) {
            float a[4], bfr[8];
            *(float4*)(a)       = *(const float4*)&Ps[k][ty * 4];
            *(float4*)(bfr)     = *(const float4*)&Vs[k][tx * 4];
            *(float4*)(bfr + 4) = *(const float4*)&Vs[k][32 + tx * 4];
#pragma unroll
            for (int i = 0; i < 4; i++)
#pragma unroll
                for (int j = 0; j < 8; j++)
                    acc[i][j] += a[i] * bfr[j];
        }
        __syncthreads();
    }

#pragma unroll
    for (int i = 0; i < 4; i++) {
        int row = rowBase + ty * 4 + i;
        float* dst = g_ctx + (size_t)b * SEQ * DMODEL + (size_t)row * DMODEL + h * HD;
        float4 r0, r1;
        r0.x = acc[i][0]; r0.y = acc[i][1]; r0.z = acc[i][2]; r0.w = acc[i][3];
        r1.x = acc[i][4]; r1.y = acc[i][5]; r1.z = acc[i][6]; r1.w = acc[i][7];
        *(float4*)&dst[tx * 4] = r0;
        *(float4*)&dst[32 + tx * 4] = r1;
    }
}

// ---------------------------------------------------------------------------
extern "C" void kernel_launch(void* const* d_in, const int* in_sizes, int n_in,
                              void* d_out, int out_size)
{
    const float* inputs_q  = (const float*)d_in[0];
    const float* inputs_kv = (const float*)d_in[1];
    const float* Wq = (const float*)d_in[2];
    const float* bq = (const float*)d_in[3];
    const float* Wk = (const float*)d_in[4];
    const float* bk = (const float*)d_in[5];
    const float* Wv = (const float*)d_in[6];
    const float* bv = (const float*)d_in[7];
    const float* Wo = (const float*)d_in[8];
    const float* bo = (const float*)d_in[9];

    float* out  = (float*)d_out;                       // [B,SQ,D]
    float* attn = out + (size_t)BB * SEQ * DMODEL;     // [B,H,SQ,SKV]

    float *q, *k, *v, *ctx;
    cudaGetSymbolAddress((void**)&q,   g_q);
    cudaGetSymbolAddress((void**)&k,   g_k);
    cudaGetSymbolAddress((void**)&v,   g_v);
    cudaGetSymbolAddress((void**)&ctx, g_ctx);

    dim3 gProj(DMODEL / 128, (BB * SEQ) / 128);        // (8, 32)

    // QKV projections
    sgemm_nn_bias<<<gProj, 256>>>(inputs_q,  Wq, bq, q, BB * SEQ, DMODEL, DMODEL);
    sgemm_nn_bias<<<gProj, 256>>>(inputs_kv, Wk, bk, k, BB * SEQ, DMODEL, DMODEL);
    sgemm_nn_bias<<<gProj, 256>>>(inputs_kv, Wv, bv, v, BB * SEQ, DMODEL, DMODEL);

    // Attention scores (pre-softmax) -> attn region of d_out
    scores_kernel<<<dim3(SEQ / 128, SEQ / 128, BB * NH), 256>>>(attn);

    // Row softmax in place
    softmax_kernel<<<BB * NH * SEQ, 256>>>(attn);

    // Context = attn @ V
    ctx_kernel<<<dim3(1, SEQ / 128, BB * NH), 256>>>(attn);

    // Output projection
    sgemm_nn_bias<<<gProj, 256>>>(ctx, Wo, bo, out, BB * SEQ, DMODEL, DMODEL);
}

// round 3
// speedup vs baseline: 3.4169x; 3.4169x over previous
#include <cuda_runtime.h>
#include <math.h>
#include <stdint.h>

#define BB 2
#define SEQ 2048
#define DMODEL 1024
#define NH 16
#define HD 64
#define QKV_ELEMS (BB * SEQ * DMODEL)

// Scratch (no allocations allowed)
__device__ float g_q[QKV_ELEMS];
__device__ float g_k[QKV_ELEMS];
__device__ float g_v[QKV_ELEMS];
__device__ float g_ctx[QKV_ELEMS];

// ---------------------------------------------------------------------------
// tf32 helpers
// ---------------------------------------------------------------------------
__device__ __forceinline__ uint32_t f2tf(float x) {
    uint32_t r;
    asm("cvt.rna.tf32.f32 %0, %1;" : "=r"(r) : "f"(x));
    return r;
}

__device__ __forceinline__ void mma8(float* c, const uint32_t* a, const uint32_t* b) {
    asm volatile(
        "mma.sync.aligned.m16n8k8.row.col.f32.tf32.tf32.f32 "
        "{%0,%1,%2,%3},{%4,%5,%6,%7},{%8,%9},{%0,%1,%2,%3};"
        : "+f"(c[0]), "+f"(c[1]), "+f"(c[2]), "+f"(c[3])
        : "r"(a[0]), "r"(a[1]), "r"(a[2]), "r"(a[3]), "r"(b[0]), "r"(b[1]));
}

// ---------------------------------------------------------------------------
// Proj GEMM (NN): C[M,N] = A[M,K] @ B[K,N] + bias[N], tf32 tensor cores.
// Block 128x128, BK=16, 256 threads, 8 warps as 4(m) x 2(n), warp tile 32x64.
// ---------------------------------------------------------------------------
__global__ __launch_bounds__(256) void proj_tf32(
    const float* __restrict__ A, const float* __restrict__ B,
    const float* __restrict__ bias, float* __restrict__ C,
    int M, int N, int K)
{
    __shared__ uint32_t As[128][20];   // stride 20 == 4 mod 32 -> conflict-free a-frags
    __shared__ uint32_t Bs[16][136];   // stride 136 == 8 mod 32 -> conflict-free b-frags

    const int tid = threadIdx.x;
    const int lane = tid & 31, wid = tid >> 5;
    const int rowBase = blockIdx.y * 128, colBase = blockIdx.x * 128;
    const int rowOff = (wid >> 1) * 32, colOff = (wid & 1) * 64;
    const int gp = lane >> 2, tig = lane & 3;

    const int ar0 = tid >> 2, ac4 = tid & 3;   // A loads: rows ar0, ar0+64
    const int bk0 = tid >> 5, bn4 = tid & 31;  // B loads: k rows bk0, bk0+8

    const float* Abase = A + (size_t)rowBase * K;

    float4 aPre[2], bPre[2];
    aPre[0] = *(const float4*)(Abase + (size_t)ar0 * K + ac4 * 4);
    aPre[1] = *(const float4*)(Abase + (size_t)(ar0 + 64) * K + ac4 * 4);
    bPre[0] = *(const float4*)(B + (size_t)bk0 * N + colBase + bn4 * 4);
    bPre[1] = *(const float4*)(B + (size_t)(bk0 + 8) * N + colBase + bn4 * 4);

    float acc[2][8][4];
#pragma unroll
    for (int t = 0; t < 2; t++)
#pragma unroll
        for (int j = 0; j < 8; j++)
#pragma unroll
            for (int q = 0; q < 4; q++) acc[t][j][q] = 0.0f;

    const int KT = K / 16;
    for (int kt = 0; kt < KT; ++kt) {
        As[ar0][ac4 * 4 + 0] = f2tf(aPre[0].x);
        As[ar0][ac4 * 4 + 1] = f2tf(aPre[0].y);
        As[ar0][ac4 * 4 + 2] = f2tf(aPre[0].z);
        As[ar0][ac4 * 4 + 3] = f2tf(aPre[0].w);
        As[ar0 + 64][ac4 * 4 + 0] = f2tf(aPre[1].x);
        As[ar0 + 64][ac4 * 4 + 1] = f2tf(aPre[1].y);
        As[ar0 + 64][ac4 * 4 + 2] = f2tf(aPre[1].z);
        As[ar0 + 64][ac4 * 4 + 3] = f2tf(aPre[1].w);
        Bs[bk0][bn4 * 4 + 0] = f2tf(bPre[0].x);
        Bs[bk0][bn4 * 4 + 1] = f2tf(bPre[0].y);
        Bs[bk0][bn4 * 4 + 2] = f2tf(bPre[0].z);
        Bs[bk0][bn4 * 4 + 3] = f2tf(bPre[0].w);
        Bs[bk0 + 8][bn4 * 4 + 0] = f2tf(bPre[1].x);
        Bs[bk0 + 8][bn4 * 4 + 1] = f2tf(bPre[1].y);
        Bs[bk0 + 8][bn4 * 4 + 2] = f2tf(bPre[1].z);
        Bs[bk0 + 8][bn4 * 4 + 3] = f2tf(bPre[1].w);
        __syncthreads();

        if (kt + 1 < KT) {
            const float* Ak = Abase + (kt + 1) * 16;
            aPre[0] = *(const float4*)(Ak + (size_t)ar0 * K + ac4 * 4);
            aPre[1] = *(const float4*)(Ak + (size_t)(ar0 + 64) * K + ac4 * 4);
            bPre[0] = *(const float4*)(B + (size_t)((kt + 1) * 16 + bk0) * N + colBase + bn4 * 4);
            bPre[1] = *(const float4*)(B + (size_t)((kt + 1) * 16 + bk0 + 8) * N + colBase + bn4 * 4);
        }

#pragma unroll
        for (int ks = 0; ks < 2; ++ks) {
            uint32_t a[2][4];
#pragma unroll
            for (int t = 0; t < 2; t++) {
                int r = rowOff + t * 16 + gp;
                a[t][0] = As[r][ks * 8 + tig];
                a[t][1] = As[r + 8][ks * 8 + tig];
                a[t][2] = As[r][ks * 8 + tig + 4];
                a[t][3] = As[r + 8][ks * 8 + tig + 4];
            }
#pragma unroll
            for (int j = 0; j < 8; j++) {
                uint32_t b[2];
                int cb = colOff + j * 8 + gp;
                b[0] = Bs[ks * 8 + tig][cb];
                b[1] = Bs[ks * 8 + tig + 4][cb];
                mma8(acc[0][j], a[0], b);
                mma8(acc[1][j], a[1], b);
            }
        }
        __syncthreads();
    }

#pragma unroll
    for (int t = 0; t < 2; t++) {
#pragma unroll
        for (int j = 0; j < 8; j++) {
            int row = rowBase + rowOff + t * 16 + gp;
            int col = colBase + colOff + j * 8 + 2 * tig;
            float2 bb = *(const float2*)&bias[col];
            float2 r0, r1;
            r0.x = acc[t][j][0] + bb.x; r0.y = acc[t][j][1] + bb.y;
            r1.x = acc[t][j][2] + bb.x; r1.y = acc[t][j][3] + bb.y;
            *(float2*)&C[(size_t)row * N + col] = r0;
            *(float2*)&C[(size_t)(row + 8) * N + col] = r1;
        }
    }
}

// ---------------------------------------------------------------------------
// Scores: S = (0.125*Q) @ K^T per (b,h), tf32. Writes pre-softmax logits.
// Block 128x128, K=HD=64 in two 32-chunks. Q scaled by 0.125 at load.
// ---------------------------------------------------------------------------
__global__ __launch_bounds__(256) void scores_tf32(float* __restrict__ attn)
{
    __shared__ uint32_t Qs[128][36];   // 36 == 4 mod 32
    __shared__ uint32_t Ks[128][36];   // stored [n][k]

    const int tid = threadIdx.x;
    const int lane = tid & 31, wid = tid >> 5;
    const int z = blockIdx.z, b = z >> 4, h = z & 15;
    const int rowBase = blockIdx.y * 128, colBase = blockIdx.x * 128;
    const int rowOff = (wid >> 1) * 32, colOff = (wid & 1) * 64;
    const int gp = lane >> 2, tig = lane & 3;

    const float* Qb = g_q + (size_t)b * SEQ * DMODEL + h * HD;
    const float* Kb = g_k + (size_t)b * SEQ * DMODEL + h * HD;

    float acc[2][8][4];
#pragma unroll
    for (int t = 0; t < 2; t++)
#pragma unroll
        for (int j = 0; j < 8; j++)
#pragma unroll
            for (int q = 0; q < 4; q++) acc[t][j][q] = 0.0f;

#pragma unroll
    for (int kc = 0; kc < 2; ++kc) {
        if (kc) __syncthreads();
#pragma unroll
        for (int i = 0; i < 4; i++) {
            int g = tid + i * 256;
            int r = g >> 3, c4 = g & 7;
            float4 qv = *(const float4*)(Qb + (size_t)(rowBase + r) * DMODEL + kc * 32 + c4 * 4);
            float4 kv = *(const float4*)(Kb + (size_t)(colBase + r) * DMODEL + kc * 32 + c4 * 4);
            Qs[r][c4 * 4 + 0] = f2tf(qv.x * 0.125f);
            Qs[r][c4 * 4 + 1] = f2tf(qv.y * 0.125f);
            Qs[r][c4 * 4 + 2] = f2tf(qv.z * 0.125f);
            Qs[r][c4 * 4 + 3] = f2tf(qv.w * 0.125f);
            Ks[r][c4 * 4 + 0] = f2tf(kv.x);
            Ks[r][c4 * 4 + 1] = f2tf(kv.y);
            Ks[r][c4 * 4 + 2] = f2tf(kv.z);
            Ks[r][c4 * 4 + 3] = f2tf(kv.w);
        }
        __syncthreads();

#pragma unroll
        for (int ks = 0; ks < 4; ++ks) {
            uint32_t a[2][4];
#pragma unroll
            for (int t = 0; t < 2; t++) {
                int r = rowOff + t * 16 + gp;
                a[t][0] = Qs[r][ks * 8 + tig];
                a[t][1] = Qs[r + 8][ks * 8 + tig];
                a[t][2] = Qs[r][ks * 8 + tig + 4];
                a[t][3] = Qs[r + 8][ks * 8 + tig + 4];
            }
#pragma unroll
            for (int j = 0; j < 8; j++) {
                uint32_t b2[2];
                int nb = colOff + j * 8 + gp;
                b2[0] = Ks[nb][ks * 8 + tig];
                b2[1] = Ks[nb][ks * 8 + tig + 4];
                mma8(acc[0][j], a[0], b2);
                mma8(acc[1][j], a[1], b2);
            }
        }
    }

    float* Cb = attn + (size_t)z * SEQ * SEQ;
#pragma unroll
    for (int t = 0; t < 2; t++) {
#pragma unroll
        for (int j = 0; j < 8; j++) {
            int row = rowBase + rowOff + t * 16 + gp;
            int col = colBase + colOff + j * 8 + 2 * tig;
            float2 r0, r1;
            r0.x = acc[t][j][0]; r0.y = acc[t][j][1];
            r1.x = acc[t][j][2]; r1.y = acc[t][j][3];
            *(float2*)&Cb[(size_t)row * SEQ + col] = r0;
            *(float2*)&Cb[(size_t)(row + 8) * SEQ + col] = r1;
        }
    }
}

// ---------------------------------------------------------------------------
// Softmax over one 2048-wide row per block, in-place.
// ---------------------------------------------------------------------------
__global__ __launch_bounds__(256) void softmax_kernel(float* __restrict__ attn)
{
    const int tid = threadIdx.x;
    float* p = attn + (size_t)blockIdx.x * SEQ;
    float4 v0 = ((const float4*)p)[tid];
    float4 v1 = ((const float4*)p)[tid + 256];

    float m = fmaxf(fmaxf(fmaxf(v0.x, v0.y), fmaxf(v0.z, v0.w)),
                    fmaxf(fmaxf(v1.x, v1.y), fmaxf(v1.z, v1.w)));
    __shared__ float red[8];
#pragma unroll
    for (int o = 16; o > 0; o >>= 1) m = fmaxf(m, __shfl_xor_sync(0xffffffffu, m, o));
    if ((tid & 31) == 0) red[tid >> 5] = m;
    __syncthreads();
    m = fmaxf(fmaxf(fmaxf(red[0], red[1]), fmaxf(red[2], red[3])),
              fmaxf(fmaxf(red[4], red[5]), fmaxf(red[6], red[7])));
    __syncthreads();

    float e[8];
    e[0] = expf(v0.x - m); e[1] = expf(v0.y - m);
    e[2] = expf(v0.z - m); e[3] = expf(v0.w - m);
    e[4] = expf(v1.x - m); e[5] = expf(v1.y - m);
    e[6] = expf(v1.z - m); e[7] = expf(v1.w - m);
    float s = ((e[0] + e[1]) + (e[2] + e[3])) + ((e[4] + e[5]) + (e[6] + e[7]));
#pragma unroll
    for (int o = 16; o > 0; o >>= 1) s += __shfl_xor_sync(0xffffffffu, s, o);
    if ((tid & 31) == 0) red[tid >> 5] = s;
    __syncthreads();
    s = ((red[0] + red[1]) + (red[2] + red[3])) + ((red[4] + red[5]) + (red[6] + red[7]));
    float inv = 1.0f / s;

    float4 w0, w1;
    w0.x = e[0] * inv; w0.y = e[1] * inv; w0.z = e[2] * inv; w0.w = e[3] * inv;
    w1.x = e[4] * inv; w1.y = e[5] * inv; w1.z = e[6] * inv; w1.w = e[7] * inv;
    ((float4*)p)[tid] = w0;
    ((float4*)p)[tid + 256] = w1;
}

// ---------------------------------------------------------------------------
// ctx = attn @ V per (b,h): [2048,2048]@[2048,64], tf32.
// Block 128x64, BK=32, 8 warps as 4(m) x 2(n), warp tile 32x32.
// ---------------------------------------------------------------------------
__global__ __launch_bounds__(256) void ctx_tf32(const float* __restrict__ attn)
{
    __shared__ uint32_t Ps[128][36];
    __shared__ uint32_t Vs[32][72];    // 72 == 8 mod 32

    const int tid = threadIdx.x;
    const int lane = tid & 31, wid = tid >> 5;
    const int z = blockIdx.y, b = z >> 4, h = z & 15;
    const int rowBase = blockIdx.x * 128;
    const int rowOff = (wid >> 1) * 32, colOff = (wid & 1) * 32;
    const int gp = lane >> 2, tig = lane & 3;

    const float* P = attn + (size_t)z * SEQ * SEQ;
    const float* V = g_v + (size_t)b * SEQ * DMODEL + h * HD;

    float acc[2][4][4];
#pragma unroll
    for (int t = 0; t < 2; t++)
#pragma unroll
        for (int j = 0; j < 4; j++)
#pragma unroll
            for (int q = 0; q < 4; q++) acc[t][j][q] = 0.0f;

    float4 pPre[4], vPre[2];
#pragma unroll
    for (int i = 0; i < 4; i++) {
        int g = tid + i * 256;
        int r = g >> 3, c4 = g & 7;
        pPre[i] = *(const float4*)(P + (size_t)(rowBase + r) * SEQ + c4 * 4);
    }
#pragma unroll
    for (int i = 0; i < 2; i++) {
        int g = tid + i * 256;
        int k = g >> 4, n4 = g & 15;
        vPre[i] = *(const float4*)(V + (size_t)k * DMODEL + n4 * 4);
    }

    const int KT = SEQ / 32;
    for (int kt = 0; kt < KT; ++kt) {
#pragma unroll
        for (int i = 0; i < 4; i++) {
            int g = tid + i * 256;
            int r = g >> 3, c4 = g & 7;
            Ps[r][c4 * 4 + 0] = f2tf(pPre[i].x);
            Ps[r][c4 * 4 + 1] = f2tf(pPre[i].y);
            Ps[r][c4 * 4 + 2] = f2tf(pPre[i].z);
            Ps[r][c4 * 4 + 3] = f2tf(pPre[i].w);
        }
#pragma unroll
        for (int i = 0; i < 2; i++) {
            int g = tid + i * 256;
            int k = g >> 4, n4 = g & 15;
            Vs[k][n4 * 4 + 0] = f2tf(vPre[i].x);
            Vs[k][n4 * 4 + 1] = f2tf(vPre[i].y);
            Vs[k][n4 * 4 + 2] = f2tf(vPre[i].z);
            Vs[k][n4 * 4 + 3] = f2tf(vPre[i].w);
        }
        __syncthreads();

        if (kt + 1 < KT) {
#pragma unroll
            for (int i = 0; i < 4; i++) {
                int g = tid + i * 256;
                int r = g >> 3, c4 = g & 7;
                pPre[i] = *(const float4*)(P + (size_t)(rowBase + r) * SEQ + (kt + 1) * 32 + c4 * 4);
            }
#pragma unroll
            for (int i = 0; i < 2; i++) {
                int g = tid + i * 256;
                int k = g >> 4, n4 = g & 15;
                vPre[i] = *(const float4*)(V + (size_t)((kt + 1) * 32 + k) * DMODEL + n4 * 4);
            }
        }

#pragma unroll
        for (int ks = 0; ks < 4; ++ks) {
            uint32_t a[2][4];
#pragma unroll
            for (int t = 0; t < 2; t++) {
                int r = rowOff + t * 16 + gp;
                a[t][0] = Ps[r][ks * 8 + tig];
                a[t][1] = Ps[r + 8][ks * 8 + tig];
                a[t][2] = Ps[r][ks * 8 + tig + 4];
                a[t][3] = Ps[r + 8][ks * 8 + tig + 4];
            }
#pragma unroll
            for (int j = 0; j < 4; j++) {
                uint32_t b2[2];
                int cb = colOff + j * 8 + gp;
                b2[0] = Vs[ks * 8 + tig][cb];
                b2[1] = Vs[ks * 8 + tig + 4][cb];
                mma8(acc[0][j], a[0], b2);
                mma8(acc[1][j], a[1], b2);
            }
        }
        __syncthreads();
    }

#pragma unroll
    for (int t = 0; t < 2; t++) {
#pragma unroll
        for (int j = 0; j < 4; j++) {
            int row = rowBase + rowOff + t * 16 + gp;
            int col = colOff + j * 8 + 2 * tig;
            float* dst0 = g_ctx + (size_t)b * SEQ * DMODEL + (size_t)row * DMODEL + h * HD + col;
            float* dst1 = g_ctx + (size_t)b * SEQ * DMODEL + (size_t)(row + 8) * DMODEL + h * HD + col;
            float2 r0, r1;
            r0.x = acc[t][j][0]; r0.y = acc[t][j][1];
            r1.x = acc[t][j][2]; r1.y = acc[t][j][3];
            *(float2*)dst0 = r0;
            *(float2*)dst1 = r1;
        }
    }
}

// ---------------------------------------------------------------------------
extern "C" void kernel_launch(void* const* d_in, const int* in_sizes, int n_in,
                              void* d_out, int out_size)
{
    const float* inputs_q  = (const float*)d_in[0];
    const float* inputs_kv = (const float*)d_in[1];
    const float* Wq = (const float*)d_in[2];
    const float* bq = (const float*)d_in[3];
    const float* Wk = (const float*)d_in[4];
    const float* bk = (const float*)d_in[5];
    const float* Wv = (const float*)d_in[6];
    const float* bv = (const float*)d_in[7];
    const float* Wo = (const float*)d_in[8];
    const float* bo = (const float*)d_in[9];

    float* out  = (float*)d_out;                       // [B,SQ,D]
    float* attn = out + (size_t)BB * SEQ * DMODEL;     // [B,H,SQ,SKV]

    float *q, *k, *v, *ctx;
    cudaGetSymbolAddress((void**)&q,   g_q);
    cudaGetSymbolAddress((void**)&k,   g_k);
    cudaGetSymbolAddress((void**)&v,   g_v);
    cudaGetSymbolAddress((void**)&ctx, g_ctx);

    dim3 gProj(DMODEL / 128, (BB * SEQ) / 128);        // (8, 32)

    proj_tf32<<<gProj, 256>>>(inputs_q,  Wq, bq, q, BB * SEQ, DMODEL, DMODEL);
    proj_tf32<<<gProj, 256>>>(inputs_kv, Wk, bk, k, BB * SEQ, DMODEL, DMODEL);
    proj_tf32<<<gProj, 256>>>(inputs_kv, Wv, bv, v, BB * SEQ, DMODEL, DMODEL);

    scores_tf32<<<dim3(SEQ / 128, SEQ / 128, BB * NH), 256>>>(attn);

    softmax_kernel<<<BB * NH * SEQ, 256>>>(attn);

    ctx_tf32<<<dim3(SEQ / 128, BB * NH), 256>>>(attn);

    proj_tf32<<<gProj, 256>>>(ctx, Wo, bo, out, BB * SEQ, DMODEL, DMODEL);
}